// round 2
// baseline (speedup 1.0000x reference)
#include <cuda_runtime.h>
#include <math.h>

// ---------------- problem constants ----------------
#define N_ATOMS    100000
#define N_BONDS_DIR 200000
#define N_BONDS    100000
#define N_ANGLES   400000
#define N_GRAPHS   2048
#define D          128
#define H          256           // 2*D
#define N_BCENT    20            // bond RBF centers: 0.0 .. 1.9 step 0.1
#define N_ACENT    32            // angle RBF centers: 0.0 .. 3.1 step 0.1
#define GAMMA      10.0f
#define LN_EPS     1e-5f

// ---------------- device scratch (allocation-free) ----------------
__device__ float g_agg[N_ATOMS * D];          // reused for both GNN blocks
__device__ float g_hidden[N_ATOMS * H];       // MLP hidden
__device__ float g_pre[N_ATOMS * D];          // pre-layernorm MLP output
__device__ float g_bond_embed[N_BONDS * D];   // undirected bond embeddings
__device__ float g_counts_a[N_GRAPHS];
__device__ float g_counts_b[N_GRAPHS];

// ---------------- zero kernels ----------------
__global__ void zero_agg_kernel() {
    int i = blockIdx.x * blockDim.x + threadIdx.x;
    float4* p = reinterpret_cast<float4*>(g_agg);
    int n4 = (N_ATOMS * D) / 4;
    if (i < n4) p[i] = make_float4(0.f, 0.f, 0.f, 0.f);
}

__global__ void zero_counts_kernel() {
    int i = blockIdx.x * blockDim.x + threadIdx.x;
    if (i < N_GRAPHS) { g_counts_a[i] = 0.f; g_counts_b[i] = 0.f; }
}

// ---------------- graph-size counts ----------------
__global__ void count_kernel(const int* __restrict__ ab_gid, const int* __restrict__ ba_gid) {
    int i = blockIdx.x * blockDim.x + threadIdx.x;
    if (i < N_ATOMS) atomicAdd(&g_counts_a[ab_gid[i]], 1.f);
    if (i < N_BONDS) atomicAdd(&g_counts_b[ba_gid[i]], 1.f);
}

// ---------------- atom-bond scatter: agg[dst] += nf[src] + ef[e] ----------------
// 32 lanes per edge, float4 per lane (128 floats per row)
__global__ void scatter_ab_kernel(const float* __restrict__ nf, const float* __restrict__ ef,
                                  const int* __restrict__ src, const int* __restrict__ dst) {
    int idx  = blockIdx.x * blockDim.x + threadIdx.x;
    int e    = idx >> 5;
    int lane = idx & 31;
    if (e >= N_BONDS_DIR) return;
    int s = src[e];
    int d = dst[e];
    float4 m = reinterpret_cast<const float4*>(nf)[(size_t)s * 32 + lane];
    float4 v = reinterpret_cast<const float4*>(ef)[(size_t)e * 32 + lane];
    m.x += v.x; m.y += v.y; m.z += v.z; m.w += v.w;
    float* p = &g_agg[(size_t)d * D + lane * 4];
    atomicAdd(p + 0, m.x);
    atomicAdd(p + 1, m.y);
    atomicAdd(p + 2, m.z);
    atomicAdd(p + 3, m.w);
}

// ---------------- bond embedding (undirected bonds, stride-2 rows) ----------------
// one block (128 threads) per undirected bond
__global__ void bond_embed_kernel(const float* __restrict__ bond_float,
                                  const int*   __restrict__ bond_cat,
                                  const float* __restrict__ bond_emb,
                                  const float* __restrict__ rbfb_W,
                                  const float* __restrict__ rbfb_b) {
    int b = blockIdx.x;          // 0..N_BONDS-1
    int f = threadIdx.x;         // 0..127
    int e2 = 2 * b;
    __shared__ float e_s[N_BCENT];
    if (f < N_BCENT) {
        float x = bond_float[e2];
        float dx = x - 0.1f * (float)f;
        e_s[f] = expf(-GAMMA * dx * dx);
    }
    __syncthreads();
    float v = rbfb_b[f];
#pragma unroll
    for (int c = 0; c < N_BCENT; c++)
        v = fmaf(e_s[c], rbfb_W[c * D + f], v);
    int c0 = bond_cat[e2 * 3 + 0];
    int c1 = bond_cat[e2 * 3 + 1];
    int c2 = bond_cat[e2 * 3 + 2];
    v += bond_emb[(0 * 16 + c0) * D + f];
    v += bond_emb[(1 * 16 + c1) * D + f];
    v += bond_emb[(2 * 16 + c2) * D + f];
    g_bond_embed[(size_t)b * D + f] = v;
}

// ---------------- bond-angle scatter with fused angle RBF ----------------
// one block (128 threads) per angle: agg[dst] += bond_embed[src] + rbf(angle)
__global__ void scatter_ba_kernel(const float* __restrict__ angle_float,
                                  const float* __restrict__ rbfa_W,
                                  const float* __restrict__ rbfa_b,
                                  const int*   __restrict__ src,
                                  const int*   __restrict__ dst) {
    int a = blockIdx.x;
    int f = threadIdx.x;
    __shared__ float e_s[N_ACENT];
    if (f < N_ACENT) {
        float x = angle_float[a];
        float dx = x - 0.1f * (float)f;
        e_s[f] = expf(-GAMMA * dx * dx);
    }
    __syncthreads();
    int s = src[a];
    int d = dst[a];
    float v = rbfa_b[f];
#pragma unroll
    for (int c = 0; c < N_ACENT; c++)
        v = fmaf(e_s[c], rbfa_W[c * D + f], v);
    v += g_bond_embed[(size_t)s * D + f];
    atomicAdd(&g_agg[(size_t)d * D + f], v);
}

// ---------------- generic fp32 tiled GEMM: C = opt_relu(A@B + bias) ----------------
// A: MxK row-major, B: KxN row-major. BM=BN=128, BK=8, 256 threads, 8x8 reg tile.
#define BM 128
#define BN 128
#define BK 8
#define TM 8
#define TN 8
__global__ __launch_bounds__(256) void gemm_kernel(const float* __restrict__ A,
                                                   const float* __restrict__ B,
                                                   const float* __restrict__ bias,
                                                   float* __restrict__ C,
                                                   int M, int N, int K, int do_relu) {
    __shared__ float As[BK][BM];
    __shared__ float Bs[BK][BN];
    int m0 = blockIdx.x * BM;
    int n0 = blockIdx.y * BN;
    int tid = threadIdx.x;
    int tx = tid & 15;   // col group: cols tx*8 .. tx*8+7
    int ty = tid >> 4;   // row group: rows ty*8 .. ty*8+7

    float acc[TM][TN];
#pragma unroll
    for (int i = 0; i < TM; i++)
#pragma unroll
        for (int j = 0; j < TN; j++) acc[i][j] = 0.f;

    int a_m = tid >> 1;          // 0..127
    int a_k = (tid & 1) * 4;     // 0 or 4
    int b_k = tid >> 5;          // 0..7
    int b_n = (tid & 31) * 4;

    for (int k0 = 0; k0 < K; k0 += BK) {
        int gm = m0 + a_m;
        float4 av = make_float4(0.f, 0.f, 0.f, 0.f);
        if (gm < M) av = *reinterpret_cast<const float4*>(&A[(size_t)gm * K + k0 + a_k]);
        As[a_k + 0][a_m] = av.x;
        As[a_k + 1][a_m] = av.y;
        As[a_k + 2][a_m] = av.z;
        As[a_k + 3][a_m] = av.w;
        float4 bv = *reinterpret_cast<const float4*>(&B[(size_t)(k0 + b_k) * N + n0 + b_n]);
        *reinterpret_cast<float4*>(&Bs[b_k][b_n]) = bv;
        __syncthreads();
#pragma unroll
        for (int kk = 0; kk < BK; kk++) {
            float af[TM], bf[TN];
            float4 af0 = *reinterpret_cast<const float4*>(&As[kk][ty * TM]);
            float4 af1 = *reinterpret_cast<const float4*>(&As[kk][ty * TM + 4]);
            af[0]=af0.x; af[1]=af0.y; af[2]=af0.z; af[3]=af0.w;
            af[4]=af1.x; af[5]=af1.y; af[6]=af1.z; af[7]=af1.w;
            float4 bf0 = *reinterpret_cast<const float4*>(&Bs[kk][tx * TN]);
            float4 bf1 = *reinterpret_cast<const float4*>(&Bs[kk][tx * TN + 4]);
            bf[0]=bf0.x; bf[1]=bf0.y; bf[2]=bf0.z; bf[3]=bf0.w;
            bf[4]=bf1.x; bf[5]=bf1.y; bf[6]=bf1.z; bf[7]=bf1.w;
#pragma unroll
            for (int i = 0; i < TM; i++)
#pragma unroll
                for (int j = 0; j < TN; j++)
                    acc[i][j] = fmaf(af[i], bf[j], acc[i][j]);
        }
        __syncthreads();
    }

#pragma unroll
    for (int i = 0; i < TM; i++) {
        int gm = m0 + ty * TM + i;
        if (gm >= M) continue;
        int gn = n0 + tx * TN;
        float4 o0, o1;
        float b0 = bias[gn + 0], b1 = bias[gn + 1], b2 = bias[gn + 2], b3 = bias[gn + 3];
        float b4 = bias[gn + 4], b5 = bias[gn + 5], b6 = bias[gn + 6], b7 = bias[gn + 7];
        o0.x = acc[i][0] + b0; o0.y = acc[i][1] + b1; o0.z = acc[i][2] + b2; o0.w = acc[i][3] + b3;
        o1.x = acc[i][4] + b4; o1.y = acc[i][5] + b5; o1.z = acc[i][6] + b6; o1.w = acc[i][7] + b7;
        if (do_relu) {
            o0.x = fmaxf(o0.x, 0.f); o0.y = fmaxf(o0.y, 0.f); o0.z = fmaxf(o0.z, 0.f); o0.w = fmaxf(o0.w, 0.f);
            o1.x = fmaxf(o1.x, 0.f); o1.y = fmaxf(o1.y, 0.f); o1.z = fmaxf(o1.z, 0.f); o1.w = fmaxf(o1.w, 0.f);
        }
        *reinterpret_cast<float4*>(&C[(size_t)gm * N + gn])     = o0;
        *reinterpret_cast<float4*>(&C[(size_t)gm * N + gn + 4]) = o1;
    }
}

// ---------------- finish: LayerNorm + SqrtGraphNorm + ReLU + residual (+opt dup) ----------------
// one block (128 threads) per row
__global__ void finish_kernel(const float* __restrict__ pre, const float* __restrict__ resid,
                              const int* __restrict__ gid, const float* __restrict__ counts,
                              const float* __restrict__ lng, const float* __restrict__ lnb,
                              float* __restrict__ out, int dup) {
    int r = blockIdx.x;
    int f = threadIdx.x;
    float v = pre[(size_t)r * D + f];

    __shared__ float red[8];
    float s = v;
#pragma unroll
    for (int o = 16; o > 0; o >>= 1) s += __shfl_xor_sync(0xffffffffu, s, o);
    if ((f & 31) == 0) red[f >> 5] = s;
    __syncthreads();
    float mu = (red[0] + red[1] + red[2] + red[3]) * (1.f / 128.f);

    float dd = v - mu;
    float s2 = dd * dd;
#pragma unroll
    for (int o = 16; o > 0; o >>= 1) s2 += __shfl_xor_sync(0xffffffffu, s2, o);
    if ((f & 31) == 0) red[4 + (f >> 5)] = s2;
    __syncthreads();
    float var = (red[4] + red[5] + red[6] + red[7]) * (1.f / 128.f);

    float y = dd * rsqrtf(var + LN_EPS) * lng[f] + lnb[f];
    y *= rsqrtf(counts[gid[r]]);
    y = fmaxf(y, 0.f);
    y += resid[(size_t)r * D + f];

    if (dup) {
        out[(size_t)(2 * r)     * D + f] = y;
        out[(size_t)(2 * r + 1) * D + f] = y;
    } else {
        out[(size_t)r * D + f] = y;
    }
}

// ---------------- host launcher ----------------
extern "C" void kernel_launch(void* const* d_in, const int* in_sizes, int n_in,
                              void* d_out, int out_size) {
    const float* node_feats  = (const float*)d_in[0];
    const float* edge_feats  = (const float*)d_in[1];
    const float* bond_float  = (const float*)d_in[2];
    const float* angle_float = (const float*)d_in[3];
    const float* bond_emb    = (const float*)d_in[4];
    const float* w1a = (const float*)d_in[5];
    const float* b1a = (const float*)d_in[6];
    const float* w2a = (const float*)d_in[7];
    const float* b2a = (const float*)d_in[8];
    const float* lng_a = (const float*)d_in[9];
    const float* lnb_a = (const float*)d_in[10];
    const float* w1b = (const float*)d_in[11];
    const float* b1b = (const float*)d_in[12];
    const float* w2b = (const float*)d_in[13];
    const float* b2b = (const float*)d_in[14];
    const float* lng_b = (const float*)d_in[15];
    const float* lnb_b = (const float*)d_in[16];
    const float* rbfb_W = (const float*)d_in[17];
    const float* rbfb_b = (const float*)d_in[18];
    const float* rbfa_W = (const float*)d_in[19];
    const float* rbfa_b = (const float*)d_in[20];
    const int* ab_src = (const int*)d_in[21];
    const int* ab_dst = (const int*)d_in[22];
    const int* ab_gid = (const int*)d_in[23];
    const int* ba_src = (const int*)d_in[24];
    const int* ba_dst = (const int*)d_in[25];
    const int* ba_gid = (const int*)d_in[26];
    const int* bond_cat = (const int*)d_in[27];

    float* out_nodes = (float*)d_out;                       // [N_ATOMS, D]
    float* out_edges = out_nodes + (size_t)N_ATOMS * D;     // [N_BONDS_DIR, D]

    // resolve device-scratch pointers BEFORE any launch (lookup only; no alloc, no sync)
    float *agg, *hidden, *pre, *bembed, *cnt_a, *cnt_b;
    cudaGetSymbolAddress((void**)&agg,    g_agg);
    cudaGetSymbolAddress((void**)&hidden, g_hidden);
    cudaGetSymbolAddress((void**)&pre,    g_pre);
    cudaGetSymbolAddress((void**)&bembed, g_bond_embed);
    cudaGetSymbolAddress((void**)&cnt_a,  g_counts_a);
    cudaGetSymbolAddress((void**)&cnt_b,  g_counts_b);

    const int zeroGrid = (N_ATOMS * D / 4 + 255) / 256;

    // ===== graph counts =====
    zero_counts_kernel<<<(N_GRAPHS + 255) / 256, 256>>>();
    count_kernel<<<(N_ATOMS + 255) / 256, 256>>>(ab_gid, ba_gid);

    // ===== atom-bond GNN block =====
    zero_agg_kernel<<<zeroGrid, 256>>>();
    scatter_ab_kernel<<<(N_BONDS_DIR * 32 + 255) / 256, 256>>>(node_feats, edge_feats, ab_src, ab_dst);

    {
        dim3 g1((N_ATOMS + BM - 1) / BM, H / BN);
        gemm_kernel<<<g1, 256>>>(agg, w1a, b1a, hidden, N_ATOMS, H, D, 1);
        dim3 g2((N_ATOMS + BM - 1) / BM, D / BN);
        gemm_kernel<<<g2, 256>>>(hidden, w2a, b2a, pre, N_ATOMS, D, H, 0);
    }
    finish_kernel<<<N_ATOMS, 128>>>(pre, node_feats, ab_gid, cnt_a, lng_a, lnb_a, out_nodes, 0);

    // ===== bond-angle GNN block =====
    bond_embed_kernel<<<N_BONDS, 128>>>(bond_float, bond_cat, bond_emb, rbfb_W, rbfb_b);
    zero_agg_kernel<<<zeroGrid, 256>>>();
    scatter_ba_kernel<<<N_ANGLES, 128>>>(angle_float, rbfa_W, rbfa_b, ba_src, ba_dst);

    {
        dim3 g1((N_BONDS + BM - 1) / BM, H / BN);
        gemm_kernel<<<g1, 256>>>(agg, w1b, b1b, hidden, N_BONDS, H, D, 1);
        dim3 g2((N_BONDS + BM - 1) / BM, D / BN);
        gemm_kernel<<<g2, 256>>>(hidden, w2b, b2b, pre, N_BONDS, D, H, 0);
    }
    finish_kernel<<<N_BONDS, 128>>>(pre, bembed, ba_gid, cnt_b, lng_b, lnb_b, out_edges, 1);
}

// round 3
// speedup vs baseline: 1.0003x; 1.0003x over previous
#include <cuda_runtime.h>
#include <math.h>

// ---------------- problem constants ----------------
#define N_ATOMS    100000
#define N_BONDS_DIR 200000
#define N_BONDS    100000
#define N_ANGLES   400000
#define N_GRAPHS   2048
#define D          128
#define H          256           // 2*D
#define N_BCENT    20            // bond RBF centers: 0.0 .. 1.9 step 0.1
#define N_ACENT    32            // angle RBF centers: 0.0 .. 3.1 step 0.1
#define GAMMA      10.0f
#define LN_EPS     1e-5f

// ---------------- device scratch (allocation-free) ----------------
__device__ float g_agg[N_ATOMS * D];          // reused for both GNN blocks
__device__ float g_hidden[N_ATOMS * H];       // MLP hidden
__device__ float g_pre[N_ATOMS * D];          // pre-layernorm MLP output
__device__ float g_bond_embed[N_BONDS * D];   // undirected bond embeddings
__device__ float g_counts_a[N_GRAPHS];
__device__ float g_counts_b[N_GRAPHS];

// ---------------- zero kernels ----------------
__global__ void zero_agg_kernel() {
    int i = blockIdx.x * blockDim.x + threadIdx.x;
    float4* p = reinterpret_cast<float4*>(g_agg);
    int n4 = (N_ATOMS * D) / 4;
    if (i < n4) p[i] = make_float4(0.f, 0.f, 0.f, 0.f);
}

__global__ void zero_counts_kernel() {
    int i = blockIdx.x * blockDim.x + threadIdx.x;
    if (i < N_GRAPHS) { g_counts_a[i] = 0.f; g_counts_b[i] = 0.f; }
}

// ---------------- graph-size counts ----------------
__global__ void count_kernel(const int* __restrict__ ab_gid, const int* __restrict__ ba_gid) {
    int i = blockIdx.x * blockDim.x + threadIdx.x;
    if (i < N_ATOMS) atomicAdd(&g_counts_a[ab_gid[i]], 1.f);
    if (i < N_BONDS) atomicAdd(&g_counts_b[ba_gid[i]], 1.f);
}

// ---------------- atom-bond scatter: agg[dst] += nf[src] + ef[e] ----------------
// 32 lanes per edge, float4 per lane (128 floats per row)
__global__ void scatter_ab_kernel(const float* __restrict__ nf, const float* __restrict__ ef,
                                  const int* __restrict__ src, const int* __restrict__ dst) {
    int idx  = blockIdx.x * blockDim.x + threadIdx.x;
    int e    = idx >> 5;
    int lane = idx & 31;
    if (e >= N_BONDS_DIR) return;
    int s = src[e];
    int d = dst[e];
    float4 m = reinterpret_cast<const float4*>(nf)[(size_t)s * 32 + lane];
    float4 v = reinterpret_cast<const float4*>(ef)[(size_t)e * 32 + lane];
    m.x += v.x; m.y += v.y; m.z += v.z; m.w += v.w;
    float* p = &g_agg[(size_t)d * D + lane * 4];
    atomicAdd(p + 0, m.x);
    atomicAdd(p + 1, m.y);
    atomicAdd(p + 2, m.z);
    atomicAdd(p + 3, m.w);
}

// ---------------- bond embedding (undirected bonds, stride-2 rows) ----------------
// one block (128 threads) per undirected bond
__global__ void bond_embed_kernel(const float* __restrict__ bond_float,
                                  const int*   __restrict__ bond_cat,
                                  const float* __restrict__ bond_emb,
                                  const float* __restrict__ rbfb_W,
                                  const float* __restrict__ rbfb_b) {
    int b = blockIdx.x;          // 0..N_BONDS-1
    int f = threadIdx.x;         // 0..127
    int e2 = 2 * b;
    __shared__ float e_s[N_BCENT];
    if (f < N_BCENT) {
        float x = bond_float[e2];
        float dx = x - 0.1f * (float)f;
        e_s[f] = expf(-GAMMA * dx * dx);
    }
    __syncthreads();
    float v = rbfb_b[f];
#pragma unroll
    for (int c = 0; c < N_BCENT; c++)
        v = fmaf(e_s[c], rbfb_W[c * D + f], v);
    int c0 = bond_cat[e2 * 3 + 0];
    int c1 = bond_cat[e2 * 3 + 1];
    int c2 = bond_cat[e2 * 3 + 2];
    v += bond_emb[(0 * 16 + c0) * D + f];
    v += bond_emb[(1 * 16 + c1) * D + f];
    v += bond_emb[(2 * 16 + c2) * D + f];
    g_bond_embed[(size_t)b * D + f] = v;
}

// ---------------- bond-angle scatter with fused angle RBF ----------------
// one block (128 threads) per angle: agg[dst] += bond_embed[src] + rbf(angle)
__global__ void scatter_ba_kernel(const float* __restrict__ angle_float,
                                  const float* __restrict__ rbfa_W,
                                  const float* __restrict__ rbfa_b,
                                  const int*   __restrict__ src,
                                  const int*   __restrict__ dst) {
    int a = blockIdx.x;
    int f = threadIdx.x;
    __shared__ float e_s[N_ACENT];
    if (f < N_ACENT) {
        float x = angle_float[a];
        float dx = x - 0.1f * (float)f;
        e_s[f] = expf(-GAMMA * dx * dx);
    }
    __syncthreads();
    int s = src[a];
    int d = dst[a];
    float v = rbfa_b[f];
#pragma unroll
    for (int c = 0; c < N_ACENT; c++)
        v = fmaf(e_s[c], rbfa_W[c * D + f], v);
    v += g_bond_embed[(size_t)s * D + f];
    atomicAdd(&g_agg[(size_t)d * D + f], v);
}

// ---------------- generic fp32 tiled GEMM: C = opt_relu(A@B + bias) ----------------
// A: MxK row-major, B: KxN row-major. BM=BN=128, BK=8, 256 threads, 8x8 reg tile.
#define BM 128
#define BN 128
#define BK 8
#define TM 8
#define TN 8
__global__ __launch_bounds__(256) void gemm_kernel(const float* __restrict__ A,
                                                   const float* __restrict__ B,
                                                   const float* __restrict__ bias,
                                                   float* __restrict__ C,
                                                   int M, int N, int K, int do_relu) {
    __shared__ float As[BK][BM];
    __shared__ float Bs[BK][BN];
    int m0 = blockIdx.x * BM;
    int n0 = blockIdx.y * BN;
    int tid = threadIdx.x;
    int tx = tid & 15;   // col group: cols tx*8 .. tx*8+7
    int ty = tid >> 4;   // row group: rows ty*8 .. ty*8+7

    float acc[TM][TN];
#pragma unroll
    for (int i = 0; i < TM; i++)
#pragma unroll
        for (int j = 0; j < TN; j++) acc[i][j] = 0.f;

    int a_m = tid >> 1;          // 0..127
    int a_k = (tid & 1) * 4;     // 0 or 4
    int b_k = tid >> 5;          // 0..7
    int b_n = (tid & 31) * 4;

    for (int k0 = 0; k0 < K; k0 += BK) {
        int gm = m0 + a_m;
        float4 av = make_float4(0.f, 0.f, 0.f, 0.f);
        if (gm < M) av = *reinterpret_cast<const float4*>(&A[(size_t)gm * K + k0 + a_k]);
        As[a_k + 0][a_m] = av.x;
        As[a_k + 1][a_m] = av.y;
        As[a_k + 2][a_m] = av.z;
        As[a_k + 3][a_m] = av.w;
        float4 bv = *reinterpret_cast<const float4*>(&B[(size_t)(k0 + b_k) * N + n0 + b_n]);
        *reinterpret_cast<float4*>(&Bs[b_k][b_n]) = bv;
        __syncthreads();
#pragma unroll
        for (int kk = 0; kk < BK; kk++) {
            float af[TM], bf[TN];
            float4 af0 = *reinterpret_cast<const float4*>(&As[kk][ty * TM]);
            float4 af1 = *reinterpret_cast<const float4*>(&As[kk][ty * TM + 4]);
            af[0]=af0.x; af[1]=af0.y; af[2]=af0.z; af[3]=af0.w;
            af[4]=af1.x; af[5]=af1.y; af[6]=af1.z; af[7]=af1.w;
            float4 bf0 = *reinterpret_cast<const float4*>(&Bs[kk][tx * TN]);
            float4 bf1 = *reinterpret_cast<const float4*>(&Bs[kk][tx * TN + 4]);
            bf[0]=bf0.x; bf[1]=bf0.y; bf[2]=bf0.z; bf[3]=bf0.w;
            bf[4]=bf1.x; bf[5]=bf1.y; bf[6]=bf1.z; bf[7]=bf1.w;
#pragma unroll
            for (int i = 0; i < TM; i++)
#pragma unroll
                for (int j = 0; j < TN; j++)
                    acc[i][j] = fmaf(af[i], bf[j], acc[i][j]);
        }
        __syncthreads();
    }

#pragma unroll
    for (int i = 0; i < TM; i++) {
        int gm = m0 + ty * TM + i;
        if (gm >= M) continue;
        int gn = n0 + tx * TN;
        float4 o0, o1;
        float b0 = bias[gn + 0], b1 = bias[gn + 1], b2 = bias[gn + 2], b3 = bias[gn + 3];
        float b4 = bias[gn + 4], b5 = bias[gn + 5], b6 = bias[gn + 6], b7 = bias[gn + 7];
        o0.x = acc[i][0] + b0; o0.y = acc[i][1] + b1; o0.z = acc[i][2] + b2; o0.w = acc[i][3] + b3;
        o1.x = acc[i][4] + b4; o1.y = acc[i][5] + b5; o1.z = acc[i][6] + b6; o1.w = acc[i][7] + b7;
        if (do_relu) {
            o0.x = fmaxf(o0.x, 0.f); o0.y = fmaxf(o0.y, 0.f); o0.z = fmaxf(o0.z, 0.f); o0.w = fmaxf(o0.w, 0.f);
            o1.x = fmaxf(o1.x, 0.f); o1.y = fmaxf(o1.y, 0.f); o1.z = fmaxf(o1.z, 0.f); o1.w = fmaxf(o1.w, 0.f);
        }
        *reinterpret_cast<float4*>(&C[(size_t)gm * N + gn])     = o0;
        *reinterpret_cast<float4*>(&C[(size_t)gm * N + gn + 4]) = o1;
    }
}

// ---------------- finish: LayerNorm + SqrtGraphNorm + ReLU + residual (+opt dup) ----------------
// one block (128 threads) per row
__global__ void finish_kernel(const float* __restrict__ pre, const float* __restrict__ resid,
                              const int* __restrict__ gid, const float* __restrict__ counts,
                              const float* __restrict__ lng, const float* __restrict__ lnb,
                              float* __restrict__ out, int dup) {
    int r = blockIdx.x;
    int f = threadIdx.x;
    float v = pre[(size_t)r * D + f];

    __shared__ float red[8];
    float s = v;
#pragma unroll
    for (int o = 16; o > 0; o >>= 1) s += __shfl_xor_sync(0xffffffffu, s, o);
    if ((f & 31) == 0) red[f >> 5] = s;
    __syncthreads();
    float mu = (red[0] + red[1] + red[2] + red[3]) * (1.f / 128.f);

    float dd = v - mu;
    float s2 = dd * dd;
#pragma unroll
    for (int o = 16; o > 0; o >>= 1) s2 += __shfl_xor_sync(0xffffffffu, s2, o);
    if ((f & 31) == 0) red[4 + (f >> 5)] = s2;
    __syncthreads();
    float var = (red[4] + red[5] + red[6] + red[7]) * (1.f / 128.f);

    float y = dd * rsqrtf(var + LN_EPS) * lng[f] + lnb[f];
    y *= rsqrtf(counts[gid[r]]);
    y = fmaxf(y, 0.f);
    y += resid[(size_t)r * D + f];

    if (dup) {
        out[(size_t)(2 * r)     * D + f] = y;
        out[(size_t)(2 * r + 1) * D + f] = y;
    } else {
        out[(size_t)r * D + f] = y;
    }
}

// ---------------- host launcher ----------------
extern "C" void kernel_launch(void* const* d_in, const int* in_sizes, int n_in,
                              void* d_out, int out_size) {
    const float* node_feats  = (const float*)d_in[0];
    const float* edge_feats  = (const float*)d_in[1];
    const float* bond_float  = (const float*)d_in[2];
    const float* angle_float = (const float*)d_in[3];
    const float* bond_emb    = (const float*)d_in[4];
    const float* w1a = (const float*)d_in[5];
    const float* b1a = (const float*)d_in[6];
    const float* w2a = (const float*)d_in[7];
    const float* b2a = (const float*)d_in[8];
    const float* lng_a = (const float*)d_in[9];
    const float* lnb_a = (const float*)d_in[10];
    const float* w1b = (const float*)d_in[11];
    const float* b1b = (const float*)d_in[12];
    const float* w2b = (const float*)d_in[13];
    const float* b2b = (const float*)d_in[14];
    const float* lng_b = (const float*)d_in[15];
    const float* lnb_b = (const float*)d_in[16];
    const float* rbfb_W = (const float*)d_in[17];
    const float* rbfb_b = (const float*)d_in[18];
    const float* rbfa_W = (const float*)d_in[19];
    const float* rbfa_b = (const float*)d_in[20];
    const int* ab_src = (const int*)d_in[21];
    const int* ab_dst = (const int*)d_in[22];
    const int* ab_gid = (const int*)d_in[23];
    const int* ba_src = (const int*)d_in[24];
    const int* ba_dst = (const int*)d_in[25];
    const int* ba_gid = (const int*)d_in[26];
    const int* bond_cat = (const int*)d_in[27];

    float* out_nodes = (float*)d_out;                       // [N_ATOMS, D]
    float* out_edges = out_nodes + (size_t)N_ATOMS * D;     // [N_BONDS_DIR, D]

    // resolve device-scratch pointers BEFORE any launch (lookup only; no alloc, no sync)
    float *agg, *hidden, *pre, *bembed, *cnt_a, *cnt_b;
    cudaGetSymbolAddress((void**)&agg,    g_agg);
    cudaGetSymbolAddress((void**)&hidden, g_hidden);
    cudaGetSymbolAddress((void**)&pre,    g_pre);
    cudaGetSymbolAddress((void**)&bembed, g_bond_embed);
    cudaGetSymbolAddress((void**)&cnt_a,  g_counts_a);
    cudaGetSymbolAddress((void**)&cnt_b,  g_counts_b);

    const int zeroGrid = (N_ATOMS * D / 4 + 255) / 256;

    // ===== graph counts =====
    zero_counts_kernel<<<(N_GRAPHS + 255) / 256, 256>>>();
    count_kernel<<<(N_ATOMS + 255) / 256, 256>>>(ab_gid, ba_gid);

    // ===== atom-bond GNN block =====
    zero_agg_kernel<<<zeroGrid, 256>>>();
    scatter_ab_kernel<<<(N_BONDS_DIR * 32 + 255) / 256, 256>>>(node_feats, edge_feats, ab_src, ab_dst);

    {
        dim3 g1((N_ATOMS + BM - 1) / BM, H / BN);
        gemm_kernel<<<g1, 256>>>(agg, w1a, b1a, hidden, N_ATOMS, H, D, 1);
        dim3 g2((N_ATOMS + BM - 1) / BM, D / BN);
        gemm_kernel<<<g2, 256>>>(hidden, w2a, b2a, pre, N_ATOMS, D, H, 0);
    }
    finish_kernel<<<N_ATOMS, 128>>>(pre, node_feats, ab_gid, cnt_a, lng_a, lnb_a, out_nodes, 0);

    // ===== bond-angle GNN block =====
    bond_embed_kernel<<<N_BONDS, 128>>>(bond_float, bond_cat, bond_emb, rbfb_W, rbfb_b);
    zero_agg_kernel<<<zeroGrid, 256>>>();
    scatter_ba_kernel<<<N_ANGLES, 128>>>(angle_float, rbfa_W, rbfa_b, ba_src, ba_dst);

    {
        dim3 g1((N_BONDS + BM - 1) / BM, H / BN);
        gemm_kernel<<<g1, 256>>>(agg, w1b, b1b, hidden, N_BONDS, H, D, 1);
        dim3 g2((N_BONDS + BM - 1) / BM, D / BN);
        gemm_kernel<<<g2, 256>>>(hidden, w2b, b2b, pre, N_BONDS, D, H, 0);
    }
    finish_kernel<<<N_BONDS, 128>>>(pre, bembed, ba_gid, cnt_b, lng_b, lnb_b, out_edges, 1);
}

// round 4
// speedup vs baseline: 1.4099x; 1.4095x over previous
#include <cuda_runtime.h>
#include <math.h>

// ---------------- problem constants ----------------
#define N_ATOMS    100000
#define N_BONDS_DIR 200000
#define N_BONDS    100000
#define N_ANGLES   400000
#define N_GRAPHS   2048
#define D          128
#define H          256           // 2*D
#define N_BCENT    20
#define N_ACENT    32
#define GAMMA      10.0f
#define LN_EPS     1e-5f

// ---------------- device scratch (allocation-free) ----------------
__device__ float g_agg[N_ATOMS * D];
__device__ float g_hidden[N_ATOMS * H];
__device__ float g_pre[N_ATOMS * D];
__device__ float g_bond_embed[N_BONDS * D];
__device__ float g_counts_a[N_GRAPHS];
__device__ float g_counts_b[N_GRAPHS];

// ---------------- zero kernels ----------------
__global__ void zero_agg_kernel() {
    int i = blockIdx.x * blockDim.x + threadIdx.x;
    float4* p = reinterpret_cast<float4*>(g_agg);
    int n4 = (N_ATOMS * D) / 4;
    if (i < n4) p[i] = make_float4(0.f, 0.f, 0.f, 0.f);
}

__global__ void zero_counts_kernel() {
    int i = blockIdx.x * blockDim.x + threadIdx.x;
    if (i < N_GRAPHS) { g_counts_a[i] = 0.f; g_counts_b[i] = 0.f; }
}

__global__ void count_kernel(const int* __restrict__ ab_gid, const int* __restrict__ ba_gid) {
    int i = blockIdx.x * blockDim.x + threadIdx.x;
    if (i < N_ATOMS) atomicAdd(&g_counts_a[ab_gid[i]], 1.f);
    if (i < N_BONDS) atomicAdd(&g_counts_b[ba_gid[i]], 1.f);
}

// ---------------- atom-bond scatter ----------------
__global__ void scatter_ab_kernel(const float* __restrict__ nf, const float* __restrict__ ef,
                                  const int* __restrict__ src, const int* __restrict__ dst) {
    int idx  = blockIdx.x * blockDim.x + threadIdx.x;
    int e    = idx >> 5;
    int lane = idx & 31;
    if (e >= N_BONDS_DIR) return;
    int s = src[e];
    int d = dst[e];
    float4 m = reinterpret_cast<const float4*>(nf)[(size_t)s * 32 + lane];
    float4 v = reinterpret_cast<const float4*>(ef)[(size_t)e * 32 + lane];
    m.x += v.x; m.y += v.y; m.z += v.z; m.w += v.w;
    float* p = &g_agg[(size_t)d * D + lane * 4];
    atomicAdd(p + 0, m.x);
    atomicAdd(p + 1, m.y);
    atomicAdd(p + 2, m.z);
    atomicAdd(p + 3, m.w);
}

// ---------------- bond embedding ----------------
__global__ void bond_embed_kernel(const float* __restrict__ bond_float,
                                  const int*   __restrict__ bond_cat,
                                  const float* __restrict__ bond_emb,
                                  const float* __restrict__ rbfb_W,
                                  const float* __restrict__ rbfb_b) {
    int b = blockIdx.x;
    int f = threadIdx.x;
    int e2 = 2 * b;
    __shared__ float e_s[N_BCENT];
    if (f < N_BCENT) {
        float x = bond_float[e2];
        float dx = x - 0.1f * (float)f;
        e_s[f] = expf(-GAMMA * dx * dx);
    }
    __syncthreads();
    float v = rbfb_b[f];
#pragma unroll
    for (int c = 0; c < N_BCENT; c++)
        v = fmaf(e_s[c], rbfb_W[c * D + f], v);
    int c0 = bond_cat[e2 * 3 + 0];
    int c1 = bond_cat[e2 * 3 + 1];
    int c2 = bond_cat[e2 * 3 + 2];
    v += bond_emb[(0 * 16 + c0) * D + f];
    v += bond_emb[(1 * 16 + c1) * D + f];
    v += bond_emb[(2 * 16 + c2) * D + f];
    g_bond_embed[(size_t)b * D + f] = v;
}

// ---------------- bond-angle scatter with fused angle RBF ----------------
__global__ void scatter_ba_kernel(const float* __restrict__ angle_float,
                                  const float* __restrict__ rbfa_W,
                                  const float* __restrict__ rbfa_b,
                                  const int*   __restrict__ src,
                                  const int*   __restrict__ dst) {
    int a = blockIdx.x;
    int f = threadIdx.x;
    __shared__ float e_s[N_ACENT];
    if (f < N_ACENT) {
        float x = angle_float[a];
        float dx = x - 0.1f * (float)f;
        e_s[f] = expf(-GAMMA * dx * dx);
    }
    __syncthreads();
    int s = src[a];
    int d = dst[a];
    float v = rbfa_b[f];
#pragma unroll
    for (int c = 0; c < N_ACENT; c++)
        v = fmaf(e_s[c], rbfa_W[c * D + f], v);
    v += g_bond_embed[(size_t)s * D + f];
    atomicAdd(&g_agg[(size_t)d * D + f], v);
}

// ---------------- TF32 tensor-core GEMM: C = opt_relu(A@B + bias) ----------------
// A: MxK row-major, B: KxN row-major.
// Tile: BM=128, BN=128, BK=16; 256 threads = 8 warps in 2(m) x 4(n); warp tile 64x32.
// mma.sync.aligned.m16n8k8.row.col.f32.tf32.tf32.f32
#define GBM 128
#define GBN 128
#define GBK 16
#define A_STRIDE (GBK + 4)    // 20 floats: distinct bank groups for 8-row x 4-col frag reads
#define B_STRIDE (GBN + 8)    // 136 floats: distinct bank groups for 4-row x 8-col frag reads

__device__ __forceinline__ unsigned f2tf32(float x) {
    unsigned r;
    asm("cvt.rna.tf32.f32 %0, %1;" : "=r"(r) : "f"(x));
    return r;
}

__device__ __forceinline__ void mma_tf32(float& c0, float& c1, float& c2, float& c3,
                                         unsigned a0, unsigned a1, unsigned a2, unsigned a3,
                                         unsigned b0, unsigned b1) {
    asm volatile(
        "mma.sync.aligned.m16n8k8.row.col.f32.tf32.tf32.f32 "
        "{%0,%1,%2,%3}, {%4,%5,%6,%7}, {%8,%9}, {%0,%1,%2,%3};\n"
        : "+f"(c0), "+f"(c1), "+f"(c2), "+f"(c3)
        : "r"(a0), "r"(a1), "r"(a2), "r"(a3), "r"(b0), "r"(b1));
}

__global__ __launch_bounds__(256) void gemm_tf32_kernel(const float* __restrict__ A,
                                                        const float* __restrict__ B,
                                                        const float* __restrict__ bias,
                                                        float* __restrict__ C,
                                                        int M, int N, int K, int do_relu) {
    __shared__ unsigned As[GBM * A_STRIDE];   // [m][k] tf32 bits
    __shared__ unsigned Bs[GBK * B_STRIDE];   // [k][n] tf32 bits

    int m0 = blockIdx.x * GBM;
    int n0 = blockIdx.y * GBN;
    int tid = threadIdx.x;
    int warp = tid >> 5;
    int lane = tid & 31;
    int gid  = lane >> 2;   // 0..7
    int tig  = lane & 3;    // 0..3
    int wm = warp >> 2;     // 0..1  (64 rows each)
    int wn = warp & 3;      // 0..3  (32 cols each)

    float acc[4][4][4];     // [mt][nt][c0..c3]
#pragma unroll
    for (int i = 0; i < 4; i++)
#pragma unroll
        for (int j = 0; j < 4; j++)
#pragma unroll
            for (int c = 0; c < 4; c++) acc[i][j][c] = 0.f;

    // A loader: thread t -> row t/2, col base (t%2)*8, two float4
    int a_r  = tid >> 1;
    int a_c  = (tid & 1) * 8;
    // B loader: thread t -> row t/16, col base (t%16)*8, two float4
    int b_r  = tid >> 4;
    int b_c  = (tid & 15) * 8;

    for (int k0 = 0; k0 < K; k0 += GBK) {
        // ---- load A tile (convert to tf32) ----
        {
            int gm = m0 + a_r;
            float4 v0 = make_float4(0.f,0.f,0.f,0.f), v1 = v0;
            if (gm < M) {
                const float4* ap = reinterpret_cast<const float4*>(&A[(size_t)gm * K + k0 + a_c]);
                v0 = ap[0]; v1 = ap[1];
            }
            unsigned* dst = &As[a_r * A_STRIDE + a_c];
            dst[0] = f2tf32(v0.x); dst[1] = f2tf32(v0.y); dst[2] = f2tf32(v0.z); dst[3] = f2tf32(v0.w);
            dst[4] = f2tf32(v1.x); dst[5] = f2tf32(v1.y); dst[6] = f2tf32(v1.z); dst[7] = f2tf32(v1.w);
        }
        // ---- load B tile (convert to tf32) ----
        {
            const float4* bp = reinterpret_cast<const float4*>(&B[(size_t)(k0 + b_r) * N + n0 + b_c]);
            float4 v0 = bp[0], v1 = bp[1];
            unsigned* dst = &Bs[b_r * B_STRIDE + b_c];
            dst[0] = f2tf32(v0.x); dst[1] = f2tf32(v0.y); dst[2] = f2tf32(v0.z); dst[3] = f2tf32(v0.w);
            dst[4] = f2tf32(v1.x); dst[5] = f2tf32(v1.y); dst[6] = f2tf32(v1.z); dst[7] = f2tf32(v1.w);
        }
        __syncthreads();

#pragma unroll
        for (int kk = 0; kk < GBK; kk += 8) {
            // B fragments for this k-step: 4 n-tiles x 2 regs
            unsigned bf[4][2];
#pragma unroll
            for (int nt = 0; nt < 4; nt++) {
                int n = wn * 32 + nt * 8 + gid;
                bf[nt][0] = Bs[(kk + tig)     * B_STRIDE + n];
                bf[nt][1] = Bs[(kk + tig + 4) * B_STRIDE + n];
            }
            // A fragments: 4 m-tiles x 4 regs
            unsigned af[4][4];
#pragma unroll
            for (int mt = 0; mt < 4; mt++) {
                int r = wm * 64 + mt * 16 + gid;
                af[mt][0] = As[r       * A_STRIDE + kk + tig];
                af[mt][1] = As[(r + 8) * A_STRIDE + kk + tig];
                af[mt][2] = As[r       * A_STRIDE + kk + tig + 4];
                af[mt][3] = As[(r + 8) * A_STRIDE + kk + tig + 4];
            }
#pragma unroll
            for (int mt = 0; mt < 4; mt++)
#pragma unroll
                for (int nt = 0; nt < 4; nt++)
                    mma_tf32(acc[mt][nt][0], acc[mt][nt][1], acc[mt][nt][2], acc[mt][nt][3],
                             af[mt][0], af[mt][1], af[mt][2], af[mt][3],
                             bf[nt][0], bf[nt][1]);
        }
        __syncthreads();
    }

    // ---- epilogue: bias (+relu), write C ----
#pragma unroll
    for (int nt = 0; nt < 4; nt++) {
        int gn = n0 + wn * 32 + nt * 8 + tig * 2;
        float bb0 = bias[gn], bb1 = bias[gn + 1];
#pragma unroll
        for (int mt = 0; mt < 4; mt++) {
            int r0 = m0 + wm * 64 + mt * 16 + gid;
            float x0 = acc[mt][nt][0] + bb0;
            float x1 = acc[mt][nt][1] + bb1;
            float x2 = acc[mt][nt][2] + bb0;
            float x3 = acc[mt][nt][3] + bb1;
            if (do_relu) {
                x0 = fmaxf(x0, 0.f); x1 = fmaxf(x1, 0.f);
                x2 = fmaxf(x2, 0.f); x3 = fmaxf(x3, 0.f);
            }
            if (r0 < M)
                *reinterpret_cast<float2*>(&C[(size_t)r0 * N + gn]) = make_float2(x0, x1);
            if (r0 + 8 < M)
                *reinterpret_cast<float2*>(&C[(size_t)(r0 + 8) * N + gn]) = make_float2(x2, x3);
        }
    }
}

// ---------------- finish: LayerNorm + SqrtGraphNorm + ReLU + residual (+opt dup) ----------------
__global__ void finish_kernel(const float* __restrict__ pre, const float* __restrict__ resid,
                              const int* __restrict__ gid, const float* __restrict__ counts,
                              const float* __restrict__ lng, const float* __restrict__ lnb,
                              float* __restrict__ out, int dup) {
    int r = blockIdx.x;
    int f = threadIdx.x;
    float v = pre[(size_t)r * D + f];

    __shared__ float red[8];
    float s = v;
#pragma unroll
    for (int o = 16; o > 0; o >>= 1) s += __shfl_xor_sync(0xffffffffu, s, o);
    if ((f & 31) == 0) red[f >> 5] = s;
    __syncthreads();
    float mu = (red[0] + red[1] + red[2] + red[3]) * (1.f / 128.f);

    float dd = v - mu;
    float s2 = dd * dd;
#pragma unroll
    for (int o = 16; o > 0; o >>= 1) s2 += __shfl_xor_sync(0xffffffffu, s2, o);
    if ((f & 31) == 0) red[4 + (f >> 5)] = s2;
    __syncthreads();
    float var = (red[4] + red[5] + red[6] + red[7]) * (1.f / 128.f);

    float y = dd * rsqrtf(var + LN_EPS) * lng[f] + lnb[f];
    y *= rsqrtf(counts[gid[r]]);
    y = fmaxf(y, 0.f);
    y += resid[(size_t)r * D + f];

    if (dup) {
        out[(size_t)(2 * r)     * D + f] = y;
        out[(size_t)(2 * r + 1) * D + f] = y;
    } else {
        out[(size_t)r * D + f] = y;
    }
}

// ---------------- host launcher ----------------
extern "C" void kernel_launch(void* const* d_in, const int* in_sizes, int n_in,
                              void* d_out, int out_size) {
    const float* node_feats  = (const float*)d_in[0];
    const float* edge_feats  = (const float*)d_in[1];
    const float* bond_float  = (const float*)d_in[2];
    const float* angle_float = (const float*)d_in[3];
    const float* bond_emb    = (const float*)d_in[4];
    const float* w1a = (const float*)d_in[5];
    const float* b1a = (const float*)d_in[6];
    const float* w2a = (const float*)d_in[7];
    const float* b2a = (const float*)d_in[8];
    const float* lng_a = (const float*)d_in[9];
    const float* lnb_a = (const float*)d_in[10];
    const float* w1b = (const float*)d_in[11];
    const float* b1b = (const float*)d_in[12];
    const float* w2b = (const float*)d_in[13];
    const float* b2b = (const float*)d_in[14];
    const float* lng_b = (const float*)d_in[15];
    const float* lnb_b = (const float*)d_in[16];
    const float* rbfb_W = (const float*)d_in[17];
    const float* rbfb_b = (const float*)d_in[18];
    const float* rbfa_W = (const float*)d_in[19];
    const float* rbfa_b = (const float*)d_in[20];
    const int* ab_src = (const int*)d_in[21];
    const int* ab_dst = (const int*)d_in[22];
    const int* ab_gid = (const int*)d_in[23];
    const int* ba_src = (const int*)d_in[24];
    const int* ba_dst = (const int*)d_in[25];
    const int* ba_gid = (const int*)d_in[26];
    const int* bond_cat = (const int*)d_in[27];

    float* out_nodes = (float*)d_out;
    float* out_edges = out_nodes + (size_t)N_ATOMS * D;

    float *agg, *hidden, *pre, *bembed, *cnt_a, *cnt_b;
    cudaGetSymbolAddress((void**)&agg,    g_agg);
    cudaGetSymbolAddress((void**)&hidden, g_hidden);
    cudaGetSymbolAddress((void**)&pre,    g_pre);
    cudaGetSymbolAddress((void**)&bembed, g_bond_embed);
    cudaGetSymbolAddress((void**)&cnt_a,  g_counts_a);
    cudaGetSymbolAddress((void**)&cnt_b,  g_counts_b);

    const int zeroGrid = (N_ATOMS * D / 4 + 255) / 256;

    // ===== graph counts =====
    zero_counts_kernel<<<(N_GRAPHS + 255) / 256, 256>>>();
    count_kernel<<<(N_ATOMS + 255) / 256, 256>>>(ab_gid, ba_gid);

    // ===== atom-bond GNN block =====
    zero_agg_kernel<<<zeroGrid, 256>>>();
    scatter_ab_kernel<<<(N_BONDS_DIR * 32 + 255) / 256, 256>>>(node_feats, edge_feats, ab_src, ab_dst);

    {
        dim3 g1((N_ATOMS + GBM - 1) / GBM, H / GBN);
        gemm_tf32_kernel<<<g1, 256>>>(agg, w1a, b1a, hidden, N_ATOMS, H, D, 1);
        dim3 g2((N_ATOMS + GBM - 1) / GBM, D / GBN);
        gemm_tf32_kernel<<<g2, 256>>>(hidden, w2a, b2a, pre, N_ATOMS, D, H, 0);
    }
    finish_kernel<<<N_ATOMS, 128>>>(pre, node_feats, ab_gid, cnt_a, lng_a, lnb_a, out_nodes, 0);

    // ===== bond-angle GNN block =====
    bond_embed_kernel<<<N_BONDS, 128>>>(bond_float, bond_cat, bond_emb, rbfb_W, rbfb_b);
    zero_agg_kernel<<<zeroGrid, 256>>>();
    scatter_ba_kernel<<<N_ANGLES, 128>>>(angle_float, rbfa_W, rbfa_b, ba_src, ba_dst);

    {
        dim3 g1((N_BONDS + GBM - 1) / GBM, H / GBN);
        gemm_tf32_kernel<<<g1, 256>>>(agg, w1b, b1b, hidden, N_BONDS, H, D, 1);
        dim3 g2((N_BONDS + GBM - 1) / GBM, D / GBN);
        gemm_tf32_kernel<<<g2, 256>>>(hidden, w2b, b2b, pre, N_BONDS, D, H, 0);
    }
    finish_kernel<<<N_BONDS, 128>>>(pre, bembed, ba_gid, cnt_b, lng_b, lnb_b, out_edges, 1);
}

// round 7
// speedup vs baseline: 1.6408x; 1.1638x over previous
#include <cuda_runtime.h>
#include <math.h>
#include <stdint.h>

// ---------------- problem constants ----------------
#define N_ATOMS    100000
#define N_BONDS_DIR 200000
#define N_BONDS    100000
#define N_ANGLES   400000
#define N_GRAPHS   2048
#define D          128
#define H          256
#define N_BCENT    20
#define N_ACENT    32
#define GAMMA      10.0f
#define LN_EPS     1e-5f

// ---------------- device scratch (allocation-free) ----------------
__device__ float g_agg[N_ATOMS * D];
__device__ float g_hidden[N_ATOMS * H];
__device__ float g_bond_embed[N_BONDS * D];
__device__ float g_counts_a[N_GRAPHS];
__device__ float g_counts_b[N_GRAPHS];

// ---------------- zero kernels ----------------
__global__ void zero_agg_kernel() {
    int i = blockIdx.x * blockDim.x + threadIdx.x;
    float4* p = reinterpret_cast<float4*>(g_agg);
    int n4 = (N_ATOMS * D) / 4;
    if (i < n4) p[i] = make_float4(0.f, 0.f, 0.f, 0.f);
}

__global__ void zero_counts_kernel() {
    int i = blockIdx.x * blockDim.x + threadIdx.x;
    if (i < N_GRAPHS) { g_counts_a[i] = 0.f; g_counts_b[i] = 0.f; }
}

__global__ void count_kernel(const int* __restrict__ ab_gid, const int* __restrict__ ba_gid) {
    int i = blockIdx.x * blockDim.x + threadIdx.x;
    if (i < N_ATOMS) atomicAdd(&g_counts_a[ab_gid[i]], 1.f);
    if (i < N_BONDS) atomicAdd(&g_counts_b[ba_gid[i]], 1.f);
}

// ---------------- atom-bond scatter ----------------
__global__ void scatter_ab_kernel(const float* __restrict__ nf, const float* __restrict__ ef,
                                  const int* __restrict__ src, const int* __restrict__ dst) {
    int idx  = blockIdx.x * blockDim.x + threadIdx.x;
    int e    = idx >> 5;
    int lane = idx & 31;
    if (e >= N_BONDS_DIR) return;
    int s = src[e];
    int d = dst[e];
    float4 m = reinterpret_cast<const float4*>(nf)[(size_t)s * 32 + lane];
    float4 v = reinterpret_cast<const float4*>(ef)[(size_t)e * 32 + lane];
    m.x += v.x; m.y += v.y; m.z += v.z; m.w += v.w;
    float* p = &g_agg[(size_t)d * D + lane * 4];
    atomicAdd(p + 0, m.x);
    atomicAdd(p + 1, m.y);
    atomicAdd(p + 2, m.z);
    atomicAdd(p + 3, m.w);
}

// ---------------- bond embedding ----------------
__global__ void bond_embed_kernel(const float* __restrict__ bond_float,
                                  const int*   __restrict__ bond_cat,
                                  const float* __restrict__ bond_emb,
                                  const float* __restrict__ rbfb_W,
                                  const float* __restrict__ rbfb_b) {
    int b = blockIdx.x;
    int f = threadIdx.x;
    int e2 = 2 * b;
    __shared__ float e_s[N_BCENT];
    if (f < N_BCENT) {
        float x = bond_float[e2];
        float dx = x - 0.1f * (float)f;
        e_s[f] = expf(-GAMMA * dx * dx);
    }
    __syncthreads();
    float v = rbfb_b[f];
#pragma unroll
    for (int c = 0; c < N_BCENT; c++)
        v = fmaf(e_s[c], rbfb_W[c * D + f], v);
    int c0 = bond_cat[e2 * 3 + 0];
    int c1 = bond_cat[e2 * 3 + 1];
    int c2 = bond_cat[e2 * 3 + 2];
    v += bond_emb[(0 * 16 + c0) * D + f];
    v += bond_emb[(1 * 16 + c1) * D + f];
    v += bond_emb[(2 * 16 + c2) * D + f];
    g_bond_embed[(size_t)b * D + f] = v;
}

// ---------------- bond-angle scatter with fused angle RBF ----------------
__global__ void scatter_ba_kernel(const float* __restrict__ angle_float,
                                  const float* __restrict__ rbfa_W,
                                  const float* __restrict__ rbfa_b,
                                  const int*   __restrict__ src,
                                  const int*   __restrict__ dst) {
    int a = blockIdx.x;
    int f = threadIdx.x;
    __shared__ float e_s[N_ACENT];
    if (f < N_ACENT) {
        float x = angle_float[a];
        float dx = x - 0.1f * (float)f;
        e_s[f] = expf(-GAMMA * dx * dx);
    }
    __syncthreads();
    int s = src[a];
    int d = dst[a];
    float v = rbfa_b[f];
#pragma unroll
    for (int c = 0; c < N_ACENT; c++)
        v = fmaf(e_s[c], rbfa_W[c * D + f], v);
    v += g_bond_embed[(size_t)s * D + f];
    atomicAdd(&g_agg[(size_t)d * D + f], v);
}

// ================= tensor-core GEMM (tf32 via raw fp32 bits) =================
// A: MxK row-major, B: KxN row-major, tile 128x128x16, cp.async double buffer.
// A row index is CLAMPED to M-1 for the partial last block (dup loads, stores guarded).
#define GBM 128
#define GBN 128
#define GBK 16
#define ASTR 20    // floats per A row slot (80B, 16B-aligned)
#define BSTR 136   // floats per B row slot (544B, 16B-aligned)

__device__ __forceinline__ void cp_async16(uint32_t dst, const void* src) {
    asm volatile("cp.async.cg.shared.global [%0], [%1], 16;\n"
                 :: "r"(dst), "l"(src));
}
__device__ __forceinline__ void cp_commit() { asm volatile("cp.async.commit_group;\n"); }
template<int N_> __device__ __forceinline__ void cp_wait() {
    asm volatile("cp.async.wait_group %0;\n" :: "n"(N_));
}

__device__ __forceinline__ void mma_tf32(float& c0, float& c1, float& c2, float& c3,
                                         unsigned a0, unsigned a1, unsigned a2, unsigned a3,
                                         unsigned b0, unsigned b1) {
    asm volatile(
        "mma.sync.aligned.m16n8k8.row.col.f32.tf32.tf32.f32 "
        "{%0,%1,%2,%3}, {%4,%5,%6,%7}, {%8,%9}, {%0,%1,%2,%3};\n"
        : "+f"(c0), "+f"(c1), "+f"(c2), "+f"(c3)
        : "r"(a0), "r"(a1), "r"(a2), "r"(a3), "r"(b0), "r"(b1));
}

// FUSE=0: C = flag?relu:id (acc + bias)   [generic N multiple of 128]
// FUSE=1: full finish epilogue (N must be 128): LN + graphnorm + relu + resid (+dup if flag)
template<int FUSE>
__global__ __launch_bounds__(256) void gemm_tc_kernel(
        const float* __restrict__ A, const float* __restrict__ B,
        const float* __restrict__ bias, float* __restrict__ C,
        const float* __restrict__ resid, const int* __restrict__ gid,
        const float* __restrict__ counts, const float* __restrict__ lng,
        const float* __restrict__ lnb,
        int M, int N, int K, int flag) {
    __shared__ float As[2 * GBM * ASTR];
    __shared__ float Bs[2 * GBK * BSTR];
    __shared__ float s_sum[GBM][4];
    __shared__ float s_sq[GBM][4];

    int m0 = blockIdx.x * GBM;
    int n0 = blockIdx.y * GBN;
    int tid = threadIdx.x;
    int warp = tid >> 5;
    int lane = tid & 31;
    int gidq = lane >> 2;   // 0..7
    int tig  = lane & 3;    // 0..3
    int wm = warp >> 2;     // 0..1
    int wn = warp & 3;      // 0..3

    float acc[4][4][4];
#pragma unroll
    for (int i = 0; i < 4; i++)
#pragma unroll
        for (int j = 0; j < 4; j++)
#pragma unroll
            for (int c = 0; c < 4; c++) acc[i][j][c] = 0.f;

    // loader mapping (A row clamped -> always-valid addresses, no predication)
    int a_r = tid >> 1;
    int a_c = (tid & 1) * 8;
    int b_r = tid >> 4;
    int b_c = (tid & 15) * 8;
    int a_row = m0 + a_r; if (a_row > M - 1) a_row = M - 1;
    const float* a_src_base = A + (size_t)a_row * K + a_c;
    const float* b_src_base = B + (size_t)b_r * N + n0 + b_c;

    uint32_t as_smem = (uint32_t)__cvta_generic_to_shared(As);
    uint32_t bs_smem = (uint32_t)__cvta_generic_to_shared(Bs);
    uint32_t a_dst = as_smem + (a_r * ASTR + a_c) * 4;
    uint32_t b_dst = bs_smem + (b_r * BSTR + b_c) * 4;

    const int nk = K / GBK;

    // prime stage 0
    cp_async16(a_dst,      a_src_base);
    cp_async16(a_dst + 16, a_src_base + 4);
    cp_async16(b_dst,      b_src_base);
    cp_async16(b_dst + 16, b_src_base + 4);
    cp_commit();

    for (int i = 0; i < nk; i++) {
        int cur = i & 1;
        if (i + 1 < nk) {
            int nxt = cur ^ 1;
            uint32_t ad = a_dst + nxt * GBM * ASTR * 4;
            uint32_t bd = b_dst + nxt * GBK * BSTR * 4;
            const float* asrc = a_src_base + (i + 1) * GBK;
            const float* bsrc = b_src_base + (size_t)(i + 1) * GBK * N;
            cp_async16(ad,      asrc);
            cp_async16(ad + 16, asrc + 4);
            cp_async16(bd,      bsrc);
            cp_async16(bd + 16, bsrc + 4);
            cp_commit();
            cp_wait<1>();
        } else {
            cp_wait<0>();
        }
        __syncthreads();

        const float* as = As + cur * GBM * ASTR;
        const float* bs = Bs + cur * GBK * BSTR;
#pragma unroll
        for (int kk = 0; kk < GBK; kk += 8) {
            unsigned bf[4][2];
#pragma unroll
            for (int nt = 0; nt < 4; nt++) {
                int n = wn * 32 + nt * 8 + gidq;
                bf[nt][0] = __float_as_uint(bs[(kk + tig)     * BSTR + n]);
                bf[nt][1] = __float_as_uint(bs[(kk + tig + 4) * BSTR + n]);
            }
            unsigned af[4][4];
#pragma unroll
            for (int mt = 0; mt < 4; mt++) {
                int r = wm * 64 + mt * 16 + gidq;
                af[mt][0] = __float_as_uint(as[r       * ASTR + kk + tig]);
                af[mt][1] = __float_as_uint(as[(r + 8) * ASTR + kk + tig]);
                af[mt][2] = __float_as_uint(as[r       * ASTR + kk + tig + 4]);
                af[mt][3] = __float_as_uint(as[(r + 8) * ASTR + kk + tig + 4]);
            }
#pragma unroll
            for (int mt = 0; mt < 4; mt++)
#pragma unroll
                for (int nt = 0; nt < 4; nt++)
                    mma_tf32(acc[mt][nt][0], acc[mt][nt][1], acc[mt][nt][2], acc[mt][nt][3],
                             af[mt][0], af[mt][1], af[mt][2], af[mt][3],
                             bf[nt][0], bf[nt][1]);
        }
        __syncthreads();
    }

    // ---- add bias (both paths) ----
#pragma unroll
    for (int nt = 0; nt < 4; nt++) {
        int gn = n0 + wn * 32 + nt * 8 + tig * 2;
        float b0 = bias[gn], b1 = bias[gn + 1];
#pragma unroll
        for (int mt = 0; mt < 4; mt++) {
            acc[mt][nt][0] += b0; acc[mt][nt][1] += b1;
            acc[mt][nt][2] += b0; acc[mt][nt][3] += b1;
        }
    }

    if (FUSE == 0) {
        // plain epilogue: optional relu, store
#pragma unroll
        for (int nt = 0; nt < 4; nt++) {
            int gn = n0 + wn * 32 + nt * 8 + tig * 2;
#pragma unroll
            for (int mt = 0; mt < 4; mt++) {
                int r0 = m0 + wm * 64 + mt * 16 + gidq;
                float x0 = acc[mt][nt][0], x1 = acc[mt][nt][1];
                float x2 = acc[mt][nt][2], x3 = acc[mt][nt][3];
                if (flag) {
                    x0 = fmaxf(x0, 0.f); x1 = fmaxf(x1, 0.f);
                    x2 = fmaxf(x2, 0.f); x3 = fmaxf(x3, 0.f);
                }
                if (r0 < M)
                    *reinterpret_cast<float2*>(&C[(size_t)r0 * N + gn]) = make_float2(x0, x1);
                if (r0 + 8 < M)
                    *reinterpret_cast<float2*>(&C[(size_t)(r0 + 8) * N + gn]) = make_float2(x2, x3);
            }
        }
    } else {
        // ---- fused LayerNorm + graphnorm + relu + residual (+dup) ----  (N == 128)
        // pass 1: row sums
#pragma unroll
        for (int mt = 0; mt < 4; mt++) {
            float s0 = 0.f, s1 = 0.f;
#pragma unroll
            for (int nt = 0; nt < 4; nt++) {
                s0 += acc[mt][nt][0] + acc[mt][nt][1];
                s1 += acc[mt][nt][2] + acc[mt][nt][3];
            }
            s0 += __shfl_xor_sync(0xffffffffu, s0, 1);
            s0 += __shfl_xor_sync(0xffffffffu, s0, 2);
            s1 += __shfl_xor_sync(0xffffffffu, s1, 1);
            s1 += __shfl_xor_sync(0xffffffffu, s1, 2);
            if (tig == 0) {
                int r = wm * 64 + mt * 16 + gidq;
                s_sum[r][wn] = s0;
                s_sum[r + 8][wn] = s1;
            }
        }
        __syncthreads();
        float mu[4][2];
#pragma unroll
        for (int mt = 0; mt < 4; mt++) {
            int r = wm * 64 + mt * 16 + gidq;
            mu[mt][0] = (s_sum[r][0] + s_sum[r][1] + s_sum[r][2] + s_sum[r][3]) * (1.f / 128.f);
            mu[mt][1] = (s_sum[r + 8][0] + s_sum[r + 8][1] + s_sum[r + 8][2] + s_sum[r + 8][3]) * (1.f / 128.f);
        }
        // pass 2: sum of squared deviations
#pragma unroll
        for (int mt = 0; mt < 4; mt++) {
            float q0 = 0.f, q1 = 0.f;
#pragma unroll
            for (int nt = 0; nt < 4; nt++) {
                float d0 = acc[mt][nt][0] - mu[mt][0]; q0 += d0 * d0;
                float d1 = acc[mt][nt][1] - mu[mt][0]; q0 += d1 * d1;
                float d2 = acc[mt][nt][2] - mu[mt][1]; q1 += d2 * d2;
                float d3 = acc[mt][nt][3] - mu[mt][1]; q1 += d3 * d3;
            }
            q0 += __shfl_xor_sync(0xffffffffu, q0, 1);
            q0 += __shfl_xor_sync(0xffffffffu, q0, 2);
            q1 += __shfl_xor_sync(0xffffffffu, q1, 1);
            q1 += __shfl_xor_sync(0xffffffffu, q1, 2);
            if (tig == 0) {
                int r = wm * 64 + mt * 16 + gidq;
                s_sq[r][wn] = q0;
                s_sq[r + 8][wn] = q1;
            }
        }
        __syncthreads();
        float rstd[4][2], cfac[4][2];
#pragma unroll
        for (int mt = 0; mt < 4; mt++) {
#pragma unroll
            for (int h = 0; h < 2; h++) {
                int r = wm * 64 + mt * 16 + gidq + h * 8;
                float var = (s_sq[r][0] + s_sq[r][1] + s_sq[r][2] + s_sq[r][3]) * (1.f / 128.f);
                rstd[mt][h] = rsqrtf(var + LN_EPS);
                int gr = m0 + r;
                cfac[mt][h] = (gr < M) ? rsqrtf(counts[gid[gr]]) : 0.f;
            }
        }
        int dup = flag;
#pragma unroll
        for (int nt = 0; nt < 4; nt++) {
            int gn = wn * 32 + nt * 8 + tig * 2;
            float g0 = lng[gn], g1 = lng[gn + 1];
            float e0 = lnb[gn], e1 = lnb[gn + 1];
#pragma unroll
            for (int mt = 0; mt < 4; mt++) {
#pragma unroll
                for (int h = 0; h < 2; h++) {
                    int r = wm * 64 + mt * 16 + gidq + h * 8;
                    int gr = m0 + r;
                    if (gr >= M) continue;
                    float v0 = acc[mt][nt][2 * h];
                    float v1 = acc[mt][nt][2 * h + 1];
                    float y0 = (v0 - mu[mt][h]) * rstd[mt][h] * g0 + e0;
                    float y1 = (v1 - mu[mt][h]) * rstd[mt][h] * g1 + e1;
                    y0 = fmaxf(y0 * cfac[mt][h], 0.f);
                    y1 = fmaxf(y1 * cfac[mt][h], 0.f);
                    float2 rr = *reinterpret_cast<const float2*>(&resid[(size_t)gr * 128 + gn]);
                    y0 += rr.x; y1 += rr.y;
                    float2 o = make_float2(y0, y1);
                    if (dup) {
                        *reinterpret_cast<float2*>(&C[(size_t)(2 * gr)     * 128 + gn]) = o;
                        *reinterpret_cast<float2*>(&C[(size_t)(2 * gr + 1) * 128 + gn]) = o;
                    } else {
                        *reinterpret_cast<float2*>(&C[(size_t)gr * 128 + gn]) = o;
                    }
                }
            }
        }
    }
}

// ---------------- host launcher ----------------
extern "C" void kernel_launch(void* const* d_in, const int* in_sizes, int n_in,
                              void* d_out, int out_size) {
    const float* node_feats  = (const float*)d_in[0];
    const float* edge_feats  = (const float*)d_in[1];
    const float* bond_float  = (const float*)d_in[2];
    const float* angle_float = (const float*)d_in[3];
    const float* bond_emb    = (const float*)d_in[4];
    const float* w1a = (const float*)d_in[5];
    const float* b1a = (const float*)d_in[6];
    const float* w2a = (const float*)d_in[7];
    const float* b2a = (const float*)d_in[8];
    const float* lng_a = (const float*)d_in[9];
    const float* lnb_a = (const float*)d_in[10];
    const float* w1b = (const float*)d_in[11];
    const float* b1b = (const float*)d_in[12];
    const float* w2b = (const float*)d_in[13];
    const float* b2b = (const float*)d_in[14];
    const float* lng_b = (const float*)d_in[15];
    const float* lnb_b = (const float*)d_in[16];
    const float* rbfb_W = (const float*)d_in[17];
    const float* rbfb_b = (const float*)d_in[18];
    const float* rbfa_W = (const float*)d_in[19];
    const float* rbfa_b = (const float*)d_in[20];
    const int* ab_src = (const int*)d_in[21];
    const int* ab_dst = (const int*)d_in[22];
    const int* ab_gid = (const int*)d_in[23];
    const int* ba_src = (const int*)d_in[24];
    const int* ba_dst = (const int*)d_in[25];
    const int* ba_gid = (const int*)d_in[26];
    const int* bond_cat = (const int*)d_in[27];

    float* out_nodes = (float*)d_out;
    float* out_edges = out_nodes + (size_t)N_ATOMS * D;

    float *agg, *hidden, *bembed, *cnt_a, *cnt_b;
    cudaGetSymbolAddress((void**)&agg,    g_agg);
    cudaGetSymbolAddress((void**)&hidden, g_hidden);
    cudaGetSymbolAddress((void**)&bembed, g_bond_embed);
    cudaGetSymbolAddress((void**)&cnt_a,  g_counts_a);
    cudaGetSymbolAddress((void**)&cnt_b,  g_counts_b);

    const int zeroGrid = (N_ATOMS * D / 4 + 255) / 256;
    const int mGrid = (N_ATOMS + GBM - 1) / GBM;   // 782 (N_ATOMS == N_BONDS)

    // ===== graph counts =====
    zero_counts_kernel<<<(N_GRAPHS + 255) / 256, 256>>>();
    count_kernel<<<(N_ATOMS + 255) / 256, 256>>>(ab_gid, ba_gid);

    // ===== atom-bond GNN block =====
    zero_agg_kernel<<<zeroGrid, 256>>>();
    scatter_ab_kernel<<<(N_BONDS_DIR * 32 + 255) / 256, 256>>>(node_feats, edge_feats, ab_src, ab_dst);

    {
        dim3 g1(mGrid, H / GBN);
        gemm_tc_kernel<0><<<g1, 256>>>(agg, w1a, b1a, hidden,
                                       nullptr, nullptr, nullptr, nullptr, nullptr,
                                       N_ATOMS, H, D, 1);
        dim3 g2(mGrid, 1);
        gemm_tc_kernel<1><<<g2, 256>>>(hidden, w2a, b2a, out_nodes,
                                       node_feats, ab_gid, cnt_a, lng_a, lnb_a,
                                       N_ATOMS, D, H, 0);
    }

    // ===== bond-angle GNN block =====
    bond_embed_kernel<<<N_BONDS, 128>>>(bond_float, bond_cat, bond_emb, rbfb_W, rbfb_b);
    zero_agg_kernel<<<zeroGrid, 256>>>();
    scatter_ba_kernel<<<N_ANGLES, 128>>>(angle_float, rbfa_W, rbfa_b, ba_src, ba_dst);

    {
        dim3 g1(mGrid, H / GBN);
        gemm_tc_kernel<0><<<g1, 256>>>(agg, w1b, b1b, hidden,
                                       nullptr, nullptr, nullptr, nullptr, nullptr,
                                       N_BONDS, H, D, 1);
        dim3 g2(mGrid, 1);
        gemm_tc_kernel<1><<<g2, 256>>>(hidden, w2b, b2b, out_edges,
                                       bembed, ba_gid, cnt_b, lng_b, lnb_b,
                                       N_BONDS, D, H, 1);
    }
}

// round 9
// speedup vs baseline: 2.0075x; 1.2235x over previous
#include <cuda_runtime.h>
#include <math.h>
#include <stdint.h>

// ---------------- problem constants ----------------
#define N_ATOMS    100000
#define N_BONDS_DIR 200000
#define N_BONDS    100000
#define N_ANGLES   400000
#define N_GRAPHS   2048
#define D          128
#define H          256
#define N_BCENT    20
#define N_ACENT    32
#define GAMMA      10.0f
#define LN_EPS     1e-5f

// ---------------- device scratch (allocation-free) ----------------
__device__ float g_agg[N_ATOMS * D];
__device__ float g_hidden[N_ATOMS * H];
__device__ float g_bond_embed[N_BONDS * D];
__device__ float g_agg_e[N_BONDS * N_ACENT];   // summed angle-RBF basis per dst bond
__device__ float g_acnt[N_BONDS];              // angle count per dst bond
__device__ float g_counts_a[N_GRAPHS];
__device__ float g_counts_b[N_GRAPHS];

// ---------------- zero kernels ----------------
__global__ void zero_agg_kernel() {
    int i = blockIdx.x * blockDim.x + threadIdx.x;
    float4* p = reinterpret_cast<float4*>(g_agg);
    int n4 = (N_ATOMS * D) / 4;
    if (i < n4) p[i] = make_float4(0.f, 0.f, 0.f, 0.f);
}

__global__ void zero_e_kernel() {
    int i = blockIdx.x * blockDim.x + threadIdx.x;
    int n4 = (N_BONDS * N_ACENT) / 4;
    if (i < n4) reinterpret_cast<float4*>(g_agg_e)[i] = make_float4(0.f, 0.f, 0.f, 0.f);
    if (i < N_BONDS) g_acnt[i] = 0.f;
}

__global__ void zero_counts_kernel() {
    int i = blockIdx.x * blockDim.x + threadIdx.x;
    if (i < N_GRAPHS) { g_counts_a[i] = 0.f; g_counts_b[i] = 0.f; }
}

__global__ void count_kernel(const int* __restrict__ ab_gid, const int* __restrict__ ba_gid) {
    int i = blockIdx.x * blockDim.x + threadIdx.x;
    if (i < N_ATOMS) atomicAdd(&g_counts_a[ab_gid[i]], 1.f);
    if (i < N_BONDS) atomicAdd(&g_counts_b[ba_gid[i]], 1.f);
}

// ---------------- atom-bond scatter ----------------
__global__ void scatter_ab_kernel(const float* __restrict__ nf, const float* __restrict__ ef,
                                  const int* __restrict__ src, const int* __restrict__ dst) {
    int idx  = blockIdx.x * blockDim.x + threadIdx.x;
    int e    = idx >> 5;
    int lane = idx & 31;
    if (e >= N_BONDS_DIR) return;
    int s = src[e];
    int d = dst[e];
    float4 m = reinterpret_cast<const float4*>(nf)[(size_t)s * 32 + lane];
    float4 v = reinterpret_cast<const float4*>(ef)[(size_t)e * 32 + lane];
    m.x += v.x; m.y += v.y; m.z += v.z; m.w += v.w;
    float* p = &g_agg[(size_t)d * D + lane * 4];
    atomicAdd(p + 0, m.x);
    atomicAdd(p + 1, m.y);
    atomicAdd(p + 2, m.z);
    atomicAdd(p + 3, m.w);
}

// ---------------- bond embedding ----------------
__global__ void bond_embed_kernel(const float* __restrict__ bond_float,
                                  const int*   __restrict__ bond_cat,
                                  const float* __restrict__ bond_emb,
                                  const float* __restrict__ rbfb_W,
                                  const float* __restrict__ rbfb_b) {
    int b = blockIdx.x;
    int f = threadIdx.x;
    int e2 = 2 * b;
    __shared__ float e_s[N_BCENT];
    if (f < N_BCENT) {
        float x = bond_float[e2];
        float dx = x - 0.1f * (float)f;
        e_s[f] = expf(-GAMMA * dx * dx);
    }
    __syncthreads();
    float v = rbfb_b[f];
#pragma unroll
    for (int c = 0; c < N_BCENT; c++)
        v = fmaf(e_s[c], rbfb_W[c * D + f], v);
    int c0 = bond_cat[e2 * 3 + 0];
    int c1 = bond_cat[e2 * 3 + 1];
    int c2 = bond_cat[e2 * 3 + 2];
    v += bond_emb[(0 * 16 + c0) * D + f];
    v += bond_emb[(1 * 16 + c1) * D + f];
    v += bond_emb[(2 * 16 + c2) * D + f];
    g_bond_embed[(size_t)b * D + f] = v;
}

// ---------------- lite bond-angle scatter (warp per angle) ----------------
// scatters 32-dim RBF basis e + angle count + bond_embed[src] row
__global__ void scatter_ba_lite_kernel(const float* __restrict__ angle_float,
                                       const int*   __restrict__ src,
                                       const int*   __restrict__ dst) {
    int a = blockIdx.x * 8 + (threadIdx.x >> 5);
    int lane = threadIdx.x & 31;
    if (a >= N_ANGLES) return;
    float x = angle_float[a];
    float dx = x - 0.1f * (float)lane;
    float e = expf(-GAMMA * dx * dx);
    int s = src[a];
    int d = dst[a];
    atomicAdd(&g_agg_e[(size_t)d * N_ACENT + lane], e);
    if (lane == 0) atomicAdd(&g_acnt[d], 1.0f);
    float4 v = reinterpret_cast<const float4*>(g_bond_embed)[(size_t)s * 32 + lane];
    float* p = &g_agg[(size_t)d * D + lane * 4];
    atomicAdd(p + 0, v.x);
    atomicAdd(p + 1, v.y);
    atomicAdd(p + 2, v.z);
    atomicAdd(p + 3, v.w);
}

// ================= tensor-core GEMM (tf32 via raw fp32 bits) =================
// A: MxK row-major, B: KxN row-major, tile 128x128x16, cp.async double buffer.
// A row index CLAMPED to M-1 for the partial last block (dup loads, stores guarded).
#define GBM 128
#define GBN 128
#define GBK 16
#define ASTR 20
#define BSTR 136

__device__ __forceinline__ void cp_async16(uint32_t dst, const void* src) {
    asm volatile("cp.async.cg.shared.global [%0], [%1], 16;\n"
                 :: "r"(dst), "l"(src));
}
__device__ __forceinline__ void cp_commit() { asm volatile("cp.async.commit_group;\n"); }
template<int N_> __device__ __forceinline__ void cp_wait() {
    asm volatile("cp.async.wait_group %0;\n" :: "n"(N_));
}

__device__ __forceinline__ void mma_tf32(float& c0, float& c1, float& c2, float& c3,
                                         unsigned a0, unsigned a1, unsigned a2, unsigned a3,
                                         unsigned b0, unsigned b1) {
    asm volatile(
        "mma.sync.aligned.m16n8k8.row.col.f32.tf32.tf32.f32 "
        "{%0,%1,%2,%3}, {%4,%5,%6,%7}, {%8,%9}, {%0,%1,%2,%3};\n"
        : "+f"(c0), "+f"(c1), "+f"(c2), "+f"(c3)
        : "r"(a0), "r"(a1), "r"(a2), "r"(a3), "r"(b0), "r"(b1));
}

// FUSE=0, ecnt==nullptr: C = flag?relu:id (acc + bias)
// FUSE=0, ecnt!=nullptr: C += acc + ecnt[row]*bias   (accumulate mode, no relu)
// FUSE=1: finish epilogue (N==128): LN + graphnorm + relu + resid (+dup if flag)
template<int FUSE>
__global__ __launch_bounds__(256) void gemm_tc_kernel(
        const float* __restrict__ A, const float* __restrict__ B,
        const float* __restrict__ bias, float* __restrict__ C,
        const float* __restrict__ resid, const int* __restrict__ gid,
        const float* __restrict__ counts, const float* __restrict__ lng,
        const float* __restrict__ lnb, const float* __restrict__ ecnt,
        int M, int N, int K, int flag) {
    __shared__ float As[2 * GBM * ASTR];
    __shared__ float Bs[2 * GBK * BSTR];
    __shared__ float s_sum[GBM][4];
    __shared__ float s_sq[GBM][4];

    int m0 = blockIdx.x * GBM;
    int n0 = blockIdx.y * GBN;
    int tid = threadIdx.x;
    int warp = tid >> 5;
    int lane = tid & 31;
    int gidq = lane >> 2;
    int tig  = lane & 3;
    int wm = warp >> 2;
    int wn = warp & 3;

    float acc[4][4][4];
#pragma unroll
    for (int i = 0; i < 4; i++)
#pragma unroll
        for (int j = 0; j < 4; j++)
#pragma unroll
            for (int c = 0; c < 4; c++) acc[i][j][c] = 0.f;

    int a_r = tid >> 1;
    int a_c = (tid & 1) * 8;
    int b_r = tid >> 4;
    int b_c = (tid & 15) * 8;
    int a_row = m0 + a_r; if (a_row > M - 1) a_row = M - 1;
    const float* a_src_base = A + (size_t)a_row * K + a_c;
    const float* b_src_base = B + (size_t)b_r * N + n0 + b_c;

    uint32_t as_smem = (uint32_t)__cvta_generic_to_shared(As);
    uint32_t bs_smem = (uint32_t)__cvta_generic_to_shared(Bs);
    uint32_t a_dst = as_smem + (a_r * ASTR + a_c) * 4;
    uint32_t b_dst = bs_smem + (b_r * BSTR + b_c) * 4;

    const int nk = K / GBK;

    cp_async16(a_dst,      a_src_base);
    cp_async16(a_dst + 16, a_src_base + 4);
    cp_async16(b_dst,      b_src_base);
    cp_async16(b_dst + 16, b_src_base + 4);
    cp_commit();

    for (int i = 0; i < nk; i++) {
        int cur = i & 1;
        if (i + 1 < nk) {
            int nxt = cur ^ 1;
            uint32_t ad = a_dst + nxt * GBM * ASTR * 4;
            uint32_t bd = b_dst + nxt * GBK * BSTR * 4;
            const float* asrc = a_src_base + (i + 1) * GBK;
            const float* bsrc = b_src_base + (size_t)(i + 1) * GBK * N;
            cp_async16(ad,      asrc);
            cp_async16(ad + 16, asrc + 4);
            cp_async16(bd,      bsrc);
            cp_async16(bd + 16, bsrc + 4);
            cp_commit();
            cp_wait<1>();
        } else {
            cp_wait<0>();
        }
        __syncthreads();

        const float* as = As + cur * GBM * ASTR;
        const float* bs = Bs + cur * GBK * BSTR;
#pragma unroll
        for (int kk = 0; kk < GBK; kk += 8) {
            unsigned bf[4][2];
#pragma unroll
            for (int nt = 0; nt < 4; nt++) {
                int n = wn * 32 + nt * 8 + gidq;
                bf[nt][0] = __float_as_uint(bs[(kk + tig)     * BSTR + n]);
                bf[nt][1] = __float_as_uint(bs[(kk + tig + 4) * BSTR + n]);
            }
            unsigned af[4][4];
#pragma unroll
            for (int mt = 0; mt < 4; mt++) {
                int r = wm * 64 + mt * 16 + gidq;
                af[mt][0] = __float_as_uint(as[r       * ASTR + kk + tig]);
                af[mt][1] = __float_as_uint(as[(r + 8) * ASTR + kk + tig]);
                af[mt][2] = __float_as_uint(as[r       * ASTR + kk + tig + 4]);
                af[mt][3] = __float_as_uint(as[(r + 8) * ASTR + kk + tig + 4]);
            }
#pragma unroll
            for (int mt = 0; mt < 4; mt++)
#pragma unroll
                for (int nt = 0; nt < 4; nt++)
                    mma_tf32(acc[mt][nt][0], acc[mt][nt][1], acc[mt][nt][2], acc[mt][nt][3],
                             af[mt][0], af[mt][1], af[mt][2], af[mt][3],
                             bf[nt][0], bf[nt][1]);
        }
        __syncthreads();
    }

    // ---- add bias (standard modes only) ----
    if (FUSE == 1 || ecnt == nullptr) {
#pragma unroll
        for (int nt = 0; nt < 4; nt++) {
            int gn = n0 + wn * 32 + nt * 8 + tig * 2;
            float b0 = bias[gn], b1 = bias[gn + 1];
#pragma unroll
            for (int mt = 0; mt < 4; mt++) {
                acc[mt][nt][0] += b0; acc[mt][nt][1] += b1;
                acc[mt][nt][2] += b0; acc[mt][nt][3] += b1;
            }
        }
    }

    if (FUSE == 0) {
        if (ecnt == nullptr) {
#pragma unroll
            for (int nt = 0; nt < 4; nt++) {
                int gn = n0 + wn * 32 + nt * 8 + tig * 2;
#pragma unroll
                for (int mt = 0; mt < 4; mt++) {
                    int r0 = m0 + wm * 64 + mt * 16 + gidq;
                    float x0 = acc[mt][nt][0], x1 = acc[mt][nt][1];
                    float x2 = acc[mt][nt][2], x3 = acc[mt][nt][3];
                    if (flag) {
                        x0 = fmaxf(x0, 0.f); x1 = fmaxf(x1, 0.f);
                        x2 = fmaxf(x2, 0.f); x3 = fmaxf(x3, 0.f);
                    }
                    if (r0 < M)
                        *reinterpret_cast<float2*>(&C[(size_t)r0 * N + gn]) = make_float2(x0, x1);
                    if (r0 + 8 < M)
                        *reinterpret_cast<float2*>(&C[(size_t)(r0 + 8) * N + gn]) = make_float2(x2, x3);
                }
            }
        } else {
            // accumulate mode: C += acc + ecnt[row]*bias
#pragma unroll
            for (int nt = 0; nt < 4; nt++) {
                int gn = n0 + wn * 32 + nt * 8 + tig * 2;
                float b0 = bias[gn], b1 = bias[gn + 1];
#pragma unroll
                for (int mt = 0; mt < 4; mt++) {
                    int r0 = m0 + wm * 64 + mt * 16 + gidq;
                    if (r0 < M) {
                        float cc = ecnt[r0];
                        float2 old = *reinterpret_cast<const float2*>(&C[(size_t)r0 * N + gn]);
                        *reinterpret_cast<float2*>(&C[(size_t)r0 * N + gn]) =
                            make_float2(acc[mt][nt][0] + cc * b0 + old.x,
                                        acc[mt][nt][1] + cc * b1 + old.y);
                    }
                    if (r0 + 8 < M) {
                        float cc = ecnt[r0 + 8];
                        float2 old = *reinterpret_cast<const float2*>(&C[(size_t)(r0 + 8) * N + gn]);
                        *reinterpret_cast<float2*>(&C[(size_t)(r0 + 8) * N + gn]) =
                            make_float2(acc[mt][nt][2] + cc * b0 + old.x,
                                        acc[mt][nt][3] + cc * b1 + old.y);
                    }
                }
            }
        }
    } else {
        // ---- fused LayerNorm + graphnorm + relu + residual (+dup) ----  (N == 128)
#pragma unroll
        for (int mt = 0; mt < 4; mt++) {
            float s0 = 0.f, s1 = 0.f;
#pragma unroll
            for (int nt = 0; nt < 4; nt++) {
                s0 += acc[mt][nt][0] + acc[mt][nt][1];
                s1 += acc[mt][nt][2] + acc[mt][nt][3];
            }
            s0 += __shfl_xor_sync(0xffffffffu, s0, 1);
            s0 += __shfl_xor_sync(0xffffffffu, s0, 2);
            s1 += __shfl_xor_sync(0xffffffffu, s1, 1);
            s1 += __shfl_xor_sync(0xffffffffu, s1, 2);
            if (tig == 0) {
                int r = wm * 64 + mt * 16 + gidq;
                s_sum[r][wn] = s0;
                s_sum[r + 8][wn] = s1;
            }
        }
        __syncthreads();
        float mu[4][2];
#pragma unroll
        for (int mt = 0; mt < 4; mt++) {
            int r = wm * 64 + mt * 16 + gidq;
            mu[mt][0] = (s_sum[r][0] + s_sum[r][1] + s_sum[r][2] + s_sum[r][3]) * (1.f / 128.f);
            mu[mt][1] = (s_sum[r + 8][0] + s_sum[r + 8][1] + s_sum[r + 8][2] + s_sum[r + 8][3]) * (1.f / 128.f);
        }
#pragma unroll
        for (int mt = 0; mt < 4; mt++) {
            float q0 = 0.f, q1 = 0.f;
#pragma unroll
            for (int nt = 0; nt < 4; nt++) {
                float d0 = acc[mt][nt][0] - mu[mt][0]; q0 += d0 * d0;
                float d1 = acc[mt][nt][1] - mu[mt][0]; q0 += d1 * d1;
                float d2 = acc[mt][nt][2] - mu[mt][1]; q1 += d2 * d2;
                float d3 = acc[mt][nt][3] - mu[mt][1]; q1 += d3 * d3;
            }
            q0 += __shfl_xor_sync(0xffffffffu, q0, 1);
            q0 += __shfl_xor_sync(0xffffffffu, q0, 2);
            q1 += __shfl_xor_sync(0xffffffffu, q1, 1);
            q1 += __shfl_xor_sync(0xffffffffu, q1, 2);
            if (tig == 0) {
                int r = wm * 64 + mt * 16 + gidq;
                s_sq[r][wn] = q0;
                s_sq[r + 8][wn] = q1;
            }
        }
        __syncthreads();
        float rstd[4][2], cfac[4][2];
#pragma unroll
        for (int mt = 0; mt < 4; mt++) {
#pragma unroll
            for (int h = 0; h < 2; h++) {
                int r = wm * 64 + mt * 16 + gidq + h * 8;
                float var = (s_sq[r][0] + s_sq[r][1] + s_sq[r][2] + s_sq[r][3]) * (1.f / 128.f);
                rstd[mt][h] = rsqrtf(var + LN_EPS);
                int gr = m0 + r;
                cfac[mt][h] = (gr < M) ? rsqrtf(counts[gid[gr]]) : 0.f;
            }
        }
        int dup = flag;
#pragma unroll
        for (int nt = 0; nt < 4; nt++) {
            int gn = wn * 32 + nt * 8 + tig * 2;
            float g0 = lng[gn], g1 = lng[gn + 1];
            float e0 = lnb[gn], e1 = lnb[gn + 1];
#pragma unroll
            for (int mt = 0; mt < 4; mt++) {
#pragma unroll
                for (int h = 0; h < 2; h++) {
                    int r = wm * 64 + mt * 16 + gidq + h * 8;
                    int gr = m0 + r;
                    if (gr >= M) continue;
                    float v0 = acc[mt][nt][2 * h];
                    float v1 = acc[mt][nt][2 * h + 1];
                    float y0 = (v0 - mu[mt][h]) * rstd[mt][h] * g0 + e0;
                    float y1 = (v1 - mu[mt][h]) * rstd[mt][h] * g1 + e1;
                    y0 = fmaxf(y0 * cfac[mt][h], 0.f);
                    y1 = fmaxf(y1 * cfac[mt][h], 0.f);
                    float2 rr = *reinterpret_cast<const float2*>(&resid[(size_t)gr * 128 + gn]);
                    y0 += rr.x; y1 += rr.y;
                    float2 o = make_float2(y0, y1);
                    if (dup) {
                        *reinterpret_cast<float2*>(&C[(size_t)(2 * gr)     * 128 + gn]) = o;
                        *reinterpret_cast<float2*>(&C[(size_t)(2 * gr + 1) * 128 + gn]) = o;
                    } else {
                        *reinterpret_cast<float2*>(&C[(size_t)gr * 128 + gn]) = o;
                    }
                }
            }
        }
    }
}

// ---------------- host launcher ----------------
extern "C" void kernel_launch(void* const* d_in, const int* in_sizes, int n_in,
                              void* d_out, int out_size) {
    const float* node_feats  = (const float*)d_in[0];
    const float* edge_feats  = (const float*)d_in[1];
    const float* bond_float  = (const float*)d_in[2];
    const float* angle_float = (const float*)d_in[3];
    const float* bond_emb    = (const float*)d_in[4];
    const float* w1a = (const float*)d_in[5];
    const float* b1a = (const float*)d_in[6];
    const float* w2a = (const float*)d_in[7];
    const float* b2a = (const float*)d_in[8];
    const float* lng_a = (const float*)d_in[9];
    const float* lnb_a = (const float*)d_in[10];
    const float* w1b = (const float*)d_in[11];
    const float* b1b = (const float*)d_in[12];
    const float* w2b = (const float*)d_in[13];
    const float* b2b = (const float*)d_in[14];
    const float* lng_b = (const float*)d_in[15];
    const float* lnb_b = (const float*)d_in[16];
    const float* rbfb_W = (const float*)d_in[17];
    const float* rbfb_b = (const float*)d_in[18];
    const float* rbfa_W = (const float*)d_in[19];
    const float* rbfa_b = (const float*)d_in[20];
    const int* ab_src = (const int*)d_in[21];
    const int* ab_dst = (const int*)d_in[22];
    const int* ab_gid = (const int*)d_in[23];
    const int* ba_src = (const int*)d_in[24];
    const int* ba_dst = (const int*)d_in[25];
    const int* ba_gid = (const int*)d_in[26];
    const int* bond_cat = (const int*)d_in[27];

    float* out_nodes = (float*)d_out;
    float* out_edges = out_nodes + (size_t)N_ATOMS * D;

    float *agg, *hidden, *bembed, *agg_e, *acnt, *cnt_a, *cnt_b;
    cudaGetSymbolAddress((void**)&agg,    g_agg);
    cudaGetSymbolAddress((void**)&hidden, g_hidden);
    cudaGetSymbolAddress((void**)&bembed, g_bond_embed);
    cudaGetSymbolAddress((void**)&agg_e,  g_agg_e);
    cudaGetSymbolAddress((void**)&acnt,   g_acnt);
    cudaGetSymbolAddress((void**)&cnt_a,  g_counts_a);
    cudaGetSymbolAddress((void**)&cnt_b,  g_counts_b);

    const int zeroGrid  = (N_ATOMS * D / 4 + 255) / 256;
    const int zeroEGrid = (N_BONDS * N_ACENT / 4 + 255) / 256;
    const int mGrid = (N_ATOMS + GBM - 1) / GBM;

    // ===== graph counts =====
    zero_counts_kernel<<<(N_GRAPHS + 255) / 256, 256>>>();
    count_kernel<<<(N_ATOMS + 255) / 256, 256>>>(ab_gid, ba_gid);

    // ===== atom-bond GNN block =====
    zero_agg_kernel<<<zeroGrid, 256>>>();
    scatter_ab_kernel<<<(N_BONDS_DIR * 32 + 255) / 256, 256>>>(node_feats, edge_feats, ab_src, ab_dst);

    {
        dim3 g1(mGrid, H / GBN);
        gemm_tc_kernel<0><<<g1, 256>>>(agg, w1a, b1a, hidden,
                                       nullptr, nullptr, nullptr, nullptr, nullptr, nullptr,
                                       N_ATOMS, H, D, 1);
        dim3 g2(mGrid, 1);
        gemm_tc_kernel<1><<<g2, 256>>>(hidden, w2a, b2a, out_nodes,
                                       node_feats, ab_gid, cnt_a, lng_a, lnb_a, nullptr,
                                       N_ATOMS, D, H, 0);
    }

    // ===== bond-angle GNN block =====
    bond_embed_kernel<<<N_BONDS, 128>>>(bond_float, bond_cat, bond_emb, rbfb_W, rbfb_b);
    zero_agg_kernel<<<zeroGrid, 256>>>();
    zero_e_kernel<<<zeroEGrid, 256>>>();
    scatter_ba_lite_kernel<<<(N_ANGLES + 7) / 8, 256>>>(angle_float, ba_src, ba_dst);
    // expand: g_agg += agg_e @ rbfa_W + acnt * rbfa_b
    {
        dim3 ge(mGrid, 1);
        gemm_tc_kernel<0><<<ge, 256>>>(agg_e, rbfa_W, rbfa_b, agg,
                                       nullptr, nullptr, nullptr, nullptr, nullptr, acnt,
                                       N_BONDS, D, N_ACENT, 0);
    }

    {
        dim3 g1(mGrid, H / GBN);
        gemm_tc_kernel<0><<<g1, 256>>>(agg, w1b, b1b, hidden,
                                       nullptr, nullptr, nullptr, nullptr, nullptr, nullptr,
                                       N_BONDS, H, D, 1);
        dim3 g2(mGrid, 1);
        gemm_tc_kernel<1><<<g2, 256>>>(hidden, w2b, b2b, out_edges,
                                       bembed, ba_gid, cnt_b, lng_b, lnb_b, nullptr,
                                       N_BONDS, D, H, 1);
    }
}